// round 3
// baseline (speedup 1.0000x reference)
#include <cuda_runtime.h>
#include <cstdint>

// ---------------- problem constants ----------------
#define T_STEPS 1024
#define TP1     1025
#define BATCH   256
#define HID     120
#define NLAYER  4
#define GATES   480        // 4*HID
#define KDIM    240        // input(120) + hidden(120)
#define NB      8          // batch slices per layer
#define NS      4          // unit slices per layer
#define BS      32         // batch per block
#define US      30         // hidden units per block
#define ROWS    120        // gate rows per block (4*US)
#define THREADS 240        // 15 row-groups x 16 batch-groups
#define NFLG    (NLAYER*TP1*NB)
// SMEM: W (KDIM x ROWS, transposed) + inp duplicated (KDIM x 64) + bias + w0
#define SMEM_FLOATS (KDIM*ROWS + KDIM*64 + 2*ROWS)
#define SMEM_BYTES  (SMEM_FLOATS*4)

// ---------------- device scratch (static: no allocs allowed) ----------------
// Full h history: h[layer][t (0..T)][b][u].  4*1025*256*120 floats ~ 504 MB.
__device__ float g_h[NLAYER * TP1 * BATCH * HID];
// Completion counters: flg[layer][t][batch-slice] counts unit-slices written.
__device__ int g_flg[NFLG];

// ---------------- helpers ----------------
__device__ __forceinline__ int ld_acq(const int* p) {
    int v;
    asm volatile("ld.global.acquire.gpu.b32 %0, [%1];" : "=r"(v) : "l"(p));
    return v;
}
__device__ __forceinline__ void red_release_add1(int* p) {
    asm volatile("red.global.release.gpu.add.s32 [%0], 1;" :: "l"(p));
}
__device__ __forceinline__ unsigned long long ffma2(
    unsigned long long a, unsigned long long b, unsigned long long c) {
    unsigned long long d;
    asm("fma.rn.f32x2 %0, %1, %2, %3;" : "=l"(d) : "l"(a), "l"(b), "l"(c));
    return d;
}
__device__ __forceinline__ float sigf(float x) {
    return __fdividef(1.0f, 1.0f + __expf(-x));
}
__device__ __forceinline__ float tanh_f(float x) {
    return 2.0f * __fdividef(1.0f, 1.0f + __expf(-2.0f * x)) - 1.0f;
}

// ---------------- flag reset ----------------
__global__ void zero_flags_kernel() {
    int i = blockIdx.x * blockDim.x + threadIdx.x;
    if (i < NFLG) g_flg[i] = 0;
}

// ---------------- persistent pipelined LSTM ----------------
// grid = 128 blocks: bid = l*32 + us*8 + bs  (one CTA per SM, all co-resident)
__global__ void __launch_bounds__(THREADS, 1) lstm_kernel(
    const float* __restrict__ x,     // (T, B)
    const float* __restrict__ h0,    // (L, B, H)
    const float* __restrict__ c0,    // (L, B, H)
    const float* __restrict__ Wih0,  // (4H, 1)
    const float* __restrict__ Wih,   // (L-1, 4H, H)
    const float* __restrict__ Whh,   // (L, 4H, H)
    const float* __restrict__ bih,   // (L, 4H)
    const float* __restrict__ bhh)   // (L, 4H)
{
    extern __shared__ float sm[];
    float* W_s    = sm;                    // [k][rr]  KDIM x ROWS (transposed)
    float* inp_s  = W_s + KDIM * ROWS;     // [k][2*b] KDIM x 64 (duplicated pairs)
    float* bias_s = inp_s + KDIM * 64;     // ROWS
    float* w0_s   = bias_s + ROWS;         // ROWS

    const int bid = blockIdx.x;
    const int l   = bid >> 5;
    const int us  = (bid >> 3) & 3;
    const int bs  = bid & 7;
    const int u0  = us * US;
    const int b0  = bs * BS;
    const int tid = threadIdx.x;

    // --- load stationary weights, TRANSPOSED: W_s[k*ROWS + rr] ---
    // local row rr = 4*uu + gate ; global gate row = gate*HID + u0 + uu
    for (int idx = tid; idx < ROWS * KDIM; idx += THREADS) {
        int k = idx / ROWS, rr = idx - k * ROWS;
        int grow = (rr & 3) * HID + u0 + (rr >> 2);
        float v;
        if (k < HID) v = (l == 0) ? 0.0f : Wih[((l - 1) * GATES + grow) * HID + k];
        else         v = Whh[(l * GATES + grow) * HID + (k - HID)];
        W_s[k * ROWS + rr] = v;
    }
    for (int rr = tid; rr < ROWS; rr += THREADS) {
        int grow = (rr & 3) * HID + u0 + (rr >> 2);
        bias_s[rr] = bih[l * GATES + grow] + bhh[l * GATES + grow];
        w0_s[rr]   = (l == 0) ? Wih0[grow] : 0.0f;
    }

    const int rg = tid >> 4;   // 0..14 : rows [rg*8, rg*8+8)
    const int bg = tid & 15;   // 0..15 : batches {2bg, 2bg+1}

    // --- init c (registers) and publish h_hist[l][0] ---
    float creg[2][2];
#pragma unroll
    for (int half = 0; half < 2; half++) {
        int u = u0 + 2 * rg + half;
#pragma unroll
        for (int b = 0; b < 2; b++) {
            int bb = b0 + 2 * bg + b;
            creg[half][b] = c0[(l * BATCH + bb) * HID + u];
            g_h[((l * TP1 + 0) * BATCH + bb) * HID + u] =
                h0[(l * BATCH + bb) * HID + u];
        }
    }
    __threadfence();
    __syncthreads();
    if (tid == 0) red_release_add1(&g_flg[(l * TP1 + 0) * NB + bs]);

    const int kstart = (l == 0) ? HID : 0;

    for (int t = 0; t < T_STEPS; t++) {
        // ---- wait for producers: EVERY thread acquires for itself ----
        while (ld_acq(&g_flg[(l * TP1 + t) * NB + bs]) < NS) {}
        if (l > 0)
            while (ld_acq(&g_flg[((l - 1) * TP1 + t + 1) * NB + bs]) < NS) {}

        // ---- stage input vector as duplicated pairs: inp_s[k*64 + 2b] = (v,v) ----
        for (int idx = tid; idx < BS * KDIM; idx += THREADS) {
            int bb = idx / KDIM, k = idx - bb * KDIM;
            float v;
            if (k < HID)
                v = (l == 0) ? 0.0f
                    : g_h[(((l - 1) * TP1 + t + 1) * BATCH + b0 + bb) * HID + k];
            else
                v = g_h[((l * TP1 + t) * BATCH + b0 + bb) * HID + (k - HID)];
            float2 vv = make_float2(v, v);
            *(float2*)&inp_s[k * 64 + 2 * bb] = vv;
        }
        __syncthreads();

        // ---- gates GEMM with packed f32x2 FMA ----
        // acc2[rp][b] = packed (row rg*8+2rp, row rg*8+2rp+1) for batch 2bg+b
        unsigned long long acc2[4][2];
#pragma unroll
        for (int i = 0; i < 4; i++) { acc2[i][0] = 0ULL; acc2[i][1] = 0ULL; }

        for (int k = kstart; k < KDIM; k += 4) {
#pragma unroll
            for (int kk = 0; kk < 4; kk++) {
                // two LDS.128: rows rg*8..rg*8+3 and rg*8+4..rg*8+7 at this k
                const ulonglong2 wA =
                    *(const ulonglong2*)&W_s[(k + kk) * ROWS + rg * 8];
                const ulonglong2 wB =
                    *(const ulonglong2*)&W_s[(k + kk) * ROWS + rg * 8 + 4];
                // duplicated inputs: (v,v) for each batch
                const unsigned long long ha =
                    *(const unsigned long long*)&inp_s[(k + kk) * 64 + 4 * bg];
                const unsigned long long hb =
                    *(const unsigned long long*)&inp_s[(k + kk) * 64 + 4 * bg + 2];
                acc2[0][0] = ffma2(wA.x, ha, acc2[0][0]);
                acc2[0][1] = ffma2(wA.x, hb, acc2[0][1]);
                acc2[1][0] = ffma2(wA.y, ha, acc2[1][0]);
                acc2[1][1] = ffma2(wA.y, hb, acc2[1][1]);
                acc2[2][0] = ffma2(wB.x, ha, acc2[2][0]);
                acc2[2][1] = ffma2(wB.x, hb, acc2[2][1]);
                acc2[3][0] = ffma2(wB.y, ha, acc2[3][0]);
                acc2[3][1] = ffma2(wB.y, hb, acc2[3][1]);
            }
        }

        // ---- elementwise cell update ----
        float xv[2];
        if (l == 0) {
            xv[0] = x[t * BATCH + b0 + 2 * bg];
            xv[1] = x[t * BATCH + b0 + 2 * bg + 1];
        }
#pragma unroll
        for (int half = 0; half < 2; half++) {
            int u = u0 + 2 * rg + half;
#pragma unroll
            for (int b = 0; b < 2; b++) {
                union { unsigned long long u64; float2 f2; } p0, p1;
                p0.u64 = acc2[half * 2 + 0][b];   // (i, f) gates
                p1.u64 = acc2[half * 2 + 1][b];   // (g, o) gates
                int r = half * 4;
                float gi = p0.f2.x + bias_s[rg * 8 + r + 0];
                float gf = p0.f2.y + bias_s[rg * 8 + r + 1];
                float gg = p1.f2.x + bias_s[rg * 8 + r + 2];
                float go = p1.f2.y + bias_s[rg * 8 + r + 3];
                if (l == 0) {
                    gi += xv[b] * w0_s[rg * 8 + r + 0];
                    gf += xv[b] * w0_s[rg * 8 + r + 1];
                    gg += xv[b] * w0_s[rg * 8 + r + 2];
                    go += xv[b] * w0_s[rg * 8 + r + 3];
                }
                float cn = sigf(gf) * creg[half][b] + sigf(gi) * tanh_f(gg);
                creg[half][b] = cn;
                float hv = sigf(go) * tanh_f(cn);
                g_h[((l * TP1 + t + 1) * BATCH + b0 + 2 * bg + b) * HID + u] = hv;
            }
        }
        __threadfence();
        __syncthreads();   // also protects inp_s WAR for next iteration
        if (tid == 0) red_release_add1(&g_flg[(l * TP1 + t + 1) * NB + bs]);
    }
}

// ---------------- output head: out[t,b] = h3[t+1,b,:] . W_lin + b_lin ----------------
__global__ void out_kernel(const float* __restrict__ Wlin,
                           const float* __restrict__ blin,
                           float* __restrict__ out)
{
    __shared__ float wsh[HID];
    __shared__ float tile[32][HID + 1];
    const int t = blockIdx.x;
    const int tid = threadIdx.x;  // 256
    if (tid < HID) wsh[tid] = Wlin[tid];
    const float bl = blin[0];
    const float* hb = &g_h[((3 * TP1 + t + 1) * BATCH) * HID];

    for (int bt = 0; bt < BATCH; bt += 32) {
        __syncthreads();
        for (int idx = tid; idx < 32 * HID; idx += 256) {
            int bb = idx / HID, u = idx - bb * HID;
            tile[bb][u] = hb[(bt + bb) * HID + u];
        }
        __syncthreads();
        int bb = tid >> 3, part = tid & 7;
        float s = 0.0f;
        for (int j = part; j < HID; j += 8) s += tile[bb][j] * wsh[j];
        s += __shfl_down_sync(0xffffffffu, s, 4);
        s += __shfl_down_sync(0xffffffffu, s, 2);
        s += __shfl_down_sync(0xffffffffu, s, 1);
        if (part == 0) out[t * BATCH + bt + bb] = s + bl;
    }
}

// ---------------- launch (3 graph nodes) ----------------
extern "C" void kernel_launch(void* const* d_in, const int* in_sizes, int n_in,
                              void* d_out, int out_size)
{
    const float* x    = (const float*)d_in[0];
    const float* h0   = (const float*)d_in[1];
    const float* c0   = (const float*)d_in[2];
    const float* Wih0 = (const float*)d_in[3];
    const float* Wih  = (const float*)d_in[4];
    const float* Whh  = (const float*)d_in[5];
    const float* bih  = (const float*)d_in[6];
    const float* bhh  = (const float*)d_in[7];
    const float* Wlin = (const float*)d_in[8];
    const float* blin = (const float*)d_in[9];
    float* out = (float*)d_out;

    cudaFuncSetAttribute(lstm_kernel,
                         cudaFuncAttributeMaxDynamicSharedMemorySize,
                         SMEM_BYTES);

    zero_flags_kernel<<<(NFLG + 255) / 256, 256>>>();
    lstm_kernel<<<NLAYER * NS * NB, THREADS, SMEM_BYTES>>>(
        x, h0, c0, Wih0, Wih, Whh, bih, bhh);
    out_kernel<<<T_STEPS, 256>>>(Wlin, blin, out);
}

// round 4
// speedup vs baseline: 1.3879x; 1.3879x over previous
#include <cuda_runtime.h>
#include <cstdint>

// ---------------- problem constants ----------------
#define T_STEPS 1024
#define TP1     1025
#define BATCH   256
#define HID     120
#define NLAYER  4
#define GATES   480        // 4*HID
#define KDIM    240        // input(120) + hidden(120)
#define NB      8          // batch slices per layer
#define NS      4          // unit slices per layer
#define BS      32         // batch per block
#define US      30         // hidden units per block
#define ROWS    120        // gate rows per block (4*US)
#define IPITCH  68         // inp row pitch in floats (16B-aligned, conflict-padded)
#define THREADS 240        // 15 row-groups x 16 batch-groups
#define NCTA    128
#define NFLG    (NLAYER*TP1*NB)
// SMEM: W (KDIM x ROWS transposed) + inp (KDIM x IPITCH dup pairs) + bias + w0 + wlin
#define SMEM_FLOATS (KDIM*ROWS + KDIM*IPITCH + 3*ROWS)
#define SMEM_BYTES  (SMEM_FLOATS*4)

// ---------------- device scratch ----------------
__device__ float g_h[NLAYER * TP1 * BATCH * HID];   // full h history (~504 MB)
__device__ int   g_flg[NFLG];                        // zero at load; re-zeroed at kernel end
__device__ int   g_done[2];                          // end-of-kernel barrier counters

// ---------------- helpers ----------------
__device__ __forceinline__ int ld_acq(const int* p) {
    int v;
    asm volatile("ld.global.acquire.gpu.b32 %0, [%1];" : "=r"(v) : "l"(p) : "memory");
    return v;
}
__device__ __forceinline__ void red_release_add1(int* p) {
    asm volatile("red.global.release.gpu.add.s32 [%0], 1;" :: "l"(p) : "memory");
}
__device__ __forceinline__ unsigned long long ffma2(
    unsigned long long a, unsigned long long b, unsigned long long c) {
    unsigned long long d;
    asm("fma.rn.f32x2 %0, %1, %2, %3;" : "=l"(d) : "l"(a), "l"(b), "l"(c));
    return d;
}
__device__ __forceinline__ float sigf(float x) {
    return __fdividef(1.0f, 1.0f + __expf(-x));
}
__device__ __forceinline__ float tanh_f(float x) {
    return 2.0f * __fdividef(1.0f, 1.0f + __expf(-2.0f * x)) - 1.0f;
}

// ---------------- single persistent kernel ----------------
// grid = 128 CTAs: bid = l*32 + us*8 + bs. One CTA per SM, all co-resident.
__global__ void __launch_bounds__(THREADS, 1) lstm_kernel(
    const float* __restrict__ x,     // (T, B)
    const float* __restrict__ h0,    // (L, B, H)
    const float* __restrict__ c0,    // (L, B, H)
    const float* __restrict__ Wih0,  // (4H, 1)
    const float* __restrict__ Wih,   // (L-1, 4H, H)
    const float* __restrict__ Whh,   // (L, 4H, H)
    const float* __restrict__ bih,   // (L, 4H)
    const float* __restrict__ bhh,   // (L, 4H)
    const float* __restrict__ Wlin,  // (1, H)
    const float* __restrict__ blin,  // (1,)
    float* __restrict__ out)         // (T, B)
{
    extern __shared__ float sm[];
    float* W_s    = sm;                    // [k][rr]  KDIM x ROWS (transposed)
    float* inp_s  = W_s + KDIM * ROWS;     // [k][2*b] KDIM x IPITCH (dup pairs)
    float* bias_s = inp_s + KDIM * IPITCH; // ROWS
    float* w0_s   = bias_s + ROWS;         // ROWS
    float* wlin_s = w0_s + ROWS;           // HID (layer-3 CTAs only)

    const int bid = blockIdx.x;
    const int l   = bid >> 5;
    const int us  = (bid >> 3) & 3;
    const int bs  = bid & 7;
    const int u0  = us * US;
    const int b0  = bs * BS;
    const int tid = threadIdx.x;

    // --- stationary weights, transposed W_s[k*ROWS + rr]; rr = 4*uu + gate ---
    for (int idx = tid; idx < ROWS * KDIM; idx += THREADS) {
        int k = idx / ROWS, rr = idx - k * ROWS;
        int grow = (rr & 3) * HID + u0 + (rr >> 2);
        float v;
        if (k < HID) v = (l == 0) ? 0.0f : Wih[((l - 1) * GATES + grow) * HID + k];
        else         v = Whh[(l * GATES + grow) * HID + (k - HID)];
        W_s[k * ROWS + rr] = v;
    }
    for (int rr = tid; rr < ROWS; rr += THREADS) {
        int grow = (rr & 3) * HID + u0 + (rr >> 2);
        bias_s[rr] = bih[l * GATES + grow] + bhh[l * GATES + grow];
        w0_s[rr]   = (l == 0) ? Wih0[grow] : 0.0f;
    }
    if (l == 3) {
        for (int u = tid; u < HID; u += THREADS) wlin_s[u] = Wlin[u];
    }
    const float bl = blin[0];

    const int rg = tid >> 4;   // 0..14 : rows [rg*8, rg*8+8)
    const int bg = tid & 15;   // 0..15 : batches {2bg, 2bg+1}

    // --- init c (registers) and publish h_hist[l][0] ---
    float creg[2][2];
#pragma unroll
    for (int half = 0; half < 2; half++) {
        int u = u0 + 2 * rg + half;
#pragma unroll
        for (int b = 0; b < 2; b++) {
            int bb = b0 + 2 * bg + b;
            creg[half][b] = c0[(l * BATCH + bb) * HID + u];
            g_h[((l * TP1 + 0) * BATCH + bb) * HID + u] =
                h0[(l * BATCH + bb) * HID + u];
        }
    }
    __syncthreads();
    if (tid == 0) red_release_add1(&g_flg[(l * TP1 + 0) * NB + bs]);

    const int kstart = (l == 0) ? HID : 0;
    const int kc = KDIM - kstart;

    for (int t = 0; t < T_STEPS; t++) {
        // ---- tid0 waits for producers (acquire), bar propagates ----
        if (tid == 0) {
            while (ld_acq(&g_flg[(l * TP1 + t) * NB + bs]) < NS) {}
            if (l > 0)
                while (ld_acq(&g_flg[((l - 1) * TP1 + t + 1) * NB + bs]) < NS) {}
        }
        __syncthreads();

        // ---- output head: h3[t] complete => out[t-1] (rotating unit-slice CTA) ----
        if (l == 3 && t > 0 && us == ((t - 1) & 3)) {
            if (tid < 128) {
                int b = tid >> 2, part = tid & 3;     // 32 batches x 4 partials
                const float* hrow =
                    &g_h[((3 * TP1 + t) * BATCH + b0 + b) * HID];
                float s = 0.0f;
#pragma unroll
                for (int j = 0; j < 30; j++) {
                    int u = part + 4 * j;
                    s += hrow[u] * wlin_s[u];
                }
                s += __shfl_down_sync(0xffffffffu, s, 2);
                s += __shfl_down_sync(0xffffffffu, s, 1);
                if (part == 0) out[(t - 1) * BATCH + b0 + b] = s + bl;
            }
        }

        // ---- stage input as duplicated pairs: inp_s[k*IPITCH + 2b] = (v,v) ----
        for (int idx = tid; idx < BS * kc; idx += THREADS) {
            int bb = idx / kc, kr = idx - bb * kc;
            int k = kstart + kr;
            float v;
            if (k < HID)
                v = g_h[(((l - 1) * TP1 + t + 1) * BATCH + b0 + bb) * HID + k];
            else
                v = g_h[((l * TP1 + t) * BATCH + b0 + bb) * HID + (k - HID)];
            *(float2*)&inp_s[k * IPITCH + 2 * bb] = make_float2(v, v);
        }
        __syncthreads();

        // ---- gates GEMM with packed f32x2 FMA; 3 LDS per k ----
        unsigned long long acc2[4][2];
#pragma unroll
        for (int i = 0; i < 4; i++) { acc2[i][0] = 0ULL; acc2[i][1] = 0ULL; }

        for (int k = kstart; k < KDIM; k += 4) {
#pragma unroll
            for (int kk = 0; kk < 4; kk++) {
                const ulonglong2 wA =
                    *(const ulonglong2*)&W_s[(k + kk) * ROWS + rg * 8];
                const ulonglong2 wB =
                    *(const ulonglong2*)&W_s[(k + kk) * ROWS + rg * 8 + 4];
                const ulonglong2 hh =
                    *(const ulonglong2*)&inp_s[(k + kk) * IPITCH + 4 * bg];
                acc2[0][0] = ffma2(wA.x, hh.x, acc2[0][0]);
                acc2[0][1] = ffma2(wA.x, hh.y, acc2[0][1]);
                acc2[1][0] = ffma2(wA.y, hh.x, acc2[1][0]);
                acc2[1][1] = ffma2(wA.y, hh.y, acc2[1][1]);
                acc2[2][0] = ffma2(wB.x, hh.x, acc2[2][0]);
                acc2[2][1] = ffma2(wB.x, hh.y, acc2[2][1]);
                acc2[3][0] = ffma2(wB.y, hh.x, acc2[3][0]);
                acc2[3][1] = ffma2(wB.y, hh.y, acc2[3][1]);
            }
        }

        // ---- elementwise cell update ----
        float xv[2];
        if (l == 0) {
            xv[0] = x[t * BATCH + b0 + 2 * bg];
            xv[1] = x[t * BATCH + b0 + 2 * bg + 1];
        }
#pragma unroll
        for (int half = 0; half < 2; half++) {
            int u = u0 + 2 * rg + half;
#pragma unroll
            for (int b = 0; b < 2; b++) {
                union { unsigned long long u64; float2 f2; } p0, p1;
                p0.u64 = acc2[half * 2 + 0][b];   // (i, f)
                p1.u64 = acc2[half * 2 + 1][b];   // (g, o)
                int r = half * 4;
                float gi = p0.f2.x + bias_s[rg * 8 + r + 0];
                float gf = p0.f2.y + bias_s[rg * 8 + r + 1];
                float gg = p1.f2.x + bias_s[rg * 8 + r + 2];
                float go = p1.f2.y + bias_s[rg * 8 + r + 3];
                if (l == 0) {
                    gi += xv[b] * w0_s[rg * 8 + r + 0];
                    gf += xv[b] * w0_s[rg * 8 + r + 1];
                    gg += xv[b] * w0_s[rg * 8 + r + 2];
                    go += xv[b] * w0_s[rg * 8 + r + 3];
                }
                float cn = sigf(gf) * creg[half][b] + sigf(gi) * tanh_f(gg);
                creg[half][b] = cn;
                float hv = sigf(go) * tanh_f(cn);
                g_h[((l * TP1 + t + 1) * BATCH + b0 + 2 * bg + b) * HID + u] = hv;
            }
        }
        __syncthreads();   // all STG h done; also WAR-protects inp_s
        if (tid == 0) red_release_add1(&g_flg[(l * TP1 + t + 1) * NB + bs]);
    }

    // ---- final output row out[T-1] (us==3 owns it per rotation) ----
    if (l == 3 && us == ((T_STEPS - 1) & 3)) {
        if (tid == 0) {
            while (ld_acq(&g_flg[(3 * TP1 + T_STEPS) * NB + bs]) < NS) {}
        }
        __syncthreads();
        if (tid < 128) {
            int b = tid >> 2, part = tid & 3;
            const float* hrow =
                &g_h[((3 * TP1 + T_STEPS) * BATCH + b0 + b) * HID];
            float s = 0.0f;
#pragma unroll
            for (int j = 0; j < 30; j++) {
                int u = part + 4 * j;
                s += hrow[u] * wlin_s[u];
            }
            s += __shfl_down_sync(0xffffffffu, s, 2);
            s += __shfl_down_sync(0xffffffffu, s, 1);
            if (part == 0) out[(T_STEPS - 1) * BATCH + b0 + b] = s + bl;
        }
    }

    // ---- global done-barrier, then reset flags for the next replay ----
    __syncthreads();
    if (tid == 0) {
        red_release_add1(&g_done[0]);
        while (ld_acq(&g_done[0]) < NCTA) {}
    }
    __syncthreads();
    for (int i = bid * THREADS + tid; i < NFLG; i += NCTA * THREADS)
        g_flg[i] = 0;
    __syncthreads();
    if (tid == 0) {
        red_release_add1(&g_done[1]);
        if (bid == 0) {
            while (ld_acq(&g_done[1]) < NCTA) {}
            g_done[0] = 0;
            g_done[1] = 0;
        }
    }
}

// ---------------- launch (ONE graph node) ----------------
extern "C" void kernel_launch(void* const* d_in, const int* in_sizes, int n_in,
                              void* d_out, int out_size)
{
    const float* x    = (const float*)d_in[0];
    const float* h0   = (const float*)d_in[1];
    const float* c0   = (const float*)d_in[2];
    const float* Wih0 = (const float*)d_in[3];
    const float* Wih  = (const float*)d_in[4];
    const float* Whh  = (const float*)d_in[5];
    const float* bih  = (const float*)d_in[6];
    const float* bhh  = (const float*)d_in[7];
    const float* Wlin = (const float*)d_in[8];
    const float* blin = (const float*)d_in[9];
    float* out = (float*)d_out;

    cudaFuncSetAttribute(lstm_kernel,
                         cudaFuncAttributeMaxDynamicSharedMemorySize,
                         SMEM_BYTES);

    lstm_kernel<<<NCTA, THREADS, SMEM_BYTES>>>(
        x, h0, c0, Wih0, Wih, Whh, bih, bhh, Wlin, blin, out);
}

// round 5
// speedup vs baseline: 1.4193x; 1.0226x over previous
#include <cuda_runtime.h>
#include <cstdint>

// ---------------- problem constants ----------------
#define T_STEPS 1024
#define TP1     1025
#define BATCH   256
#define HID     120
#define NLAYER  4
#define GATES   480        // 4*HID
#define KDIM    240        // input(120) + hidden(120)
#define NB      8          // batch slices per layer
#define NS      4          // unit slices per layer
#define BS      32         // batch per block
#define US      30         // hidden units per block
#define ROWS    120        // gate rows per block (4*US)
#define IPITCH  68         // inp row pitch in floats (16B-aligned, conflict-padded)
#define THREADS 240        // 15 row-groups x 16 batch-groups
#define NCTA    128
#define NFLG    (NLAYER*TP1*NB)
// SMEM: W (KDIM x ROWS transposed) + inp (KDIM x IPITCH dup pairs) + bias + w0 + wlin
#define SMEM_FLOATS (KDIM*ROWS + KDIM*IPITCH + 3*ROWS)
#define SMEM_BYTES  (SMEM_FLOATS*4)

// ---------------- device scratch ----------------
__device__ float g_h[NLAYER * TP1 * BATCH * HID];   // full h history (~504 MB)
__device__ int   g_flg[NFLG];                        // zero at load; re-zeroed at kernel end
__device__ int   g_done[2];                          // end-of-kernel barrier counters

// ---------------- helpers ----------------
__device__ __forceinline__ int ld_acq(const int* p) {
    int v;
    asm volatile("ld.global.acquire.gpu.b32 %0, [%1];" : "=r"(v) : "l"(p) : "memory");
    return v;
}
__device__ __forceinline__ void red_release_add1(int* p) {
    asm volatile("red.global.release.gpu.add.s32 [%0], 1;" :: "l"(p) : "memory");
}
__device__ __forceinline__ unsigned long long ffma2(
    unsigned long long a, unsigned long long b, unsigned long long c) {
    unsigned long long d;
    asm("fma.rn.f32x2 %0, %1, %2, %3;" : "=l"(d) : "l"(a), "l"(b), "l"(c));
    return d;
}
__device__ __forceinline__ float sigf(float x) {
    return __fdividef(1.0f, 1.0f + __expf(-x));
}
__device__ __forceinline__ float tanh_f(float x) {
    return 2.0f * __fdividef(1.0f, 1.0f + __expf(-2.0f * x)) - 1.0f;
}

// ---------------- single persistent kernel ----------------
// grid = 128 CTAs: bid = l*32 + us*8 + bs. One CTA per SM, all co-resident.
__global__ void __launch_bounds__(THREADS, 1) lstm_kernel(
    const float* __restrict__ x,     // (T, B)
    const float* __restrict__ h0,    // (L, B, H)
    const float* __restrict__ c0,    // (L, B, H)
    const float* __restrict__ Wih0,  // (4H, 1)
    const float* __restrict__ Wih,   // (L-1, 4H, H)
    const float* __restrict__ Whh,   // (L, 4H, H)
    const float* __restrict__ bih,   // (L, 4H)
    const float* __restrict__ bhh,   // (L, 4H)
    const float* __restrict__ Wlin,  // (1, H)
    const float* __restrict__ blin,  // (1,)
    float* __restrict__ out)         // (T, B)
{
    extern __shared__ float sm[];
    float* W_s    = sm;                    // [k][rr]  KDIM x ROWS (transposed)
    float* inp_s  = W_s + KDIM * ROWS;     // [k][2*b] KDIM x IPITCH (dup pairs)
    float* bias_s = inp_s + KDIM * IPITCH; // ROWS
    float* w0_s   = bias_s + ROWS;         // ROWS
    float* wlin_s = w0_s + ROWS;           // HID (layer-3 CTAs only)

    const int bid = blockIdx.x;
    const int l   = bid >> 5;
    const int us  = (bid >> 3) & 3;
    const int bs  = bid & 7;
    const int u0  = us * US;
    const int b0  = bs * BS;
    const int tid = threadIdx.x;

    // --- stationary weights, transposed W_s[k*ROWS + rr]; rr = 4*uu + gate ---
    for (int idx = tid; idx < ROWS * KDIM; idx += THREADS) {
        int k = idx / ROWS, rr = idx - k * ROWS;
        int grow = (rr & 3) * HID + u0 + (rr >> 2);
        float v;
        if (k < HID) v = (l == 0) ? 0.0f : Wih[((l - 1) * GATES + grow) * HID + k];
        else         v = Whh[(l * GATES + grow) * HID + (k - HID)];
        W_s[k * ROWS + rr] = v;
    }
    for (int rr = tid; rr < ROWS; rr += THREADS) {
        int grow = (rr & 3) * HID + u0 + (rr >> 2);
        bias_s[rr] = bih[l * GATES + grow] + bhh[l * GATES + grow];
        w0_s[rr]   = (l == 0) ? Wih0[grow] : 0.0f;
    }
    if (l == 3) {
        for (int u = tid; u < HID; u += THREADS) wlin_s[u] = Wlin[u];
    }
    const float bl = blin[0];

    const int rg = tid >> 4;   // 0..14 : rows [rg*8, rg*8+8)
    const int bg = tid & 15;   // 0..15 : batches {2bg, 2bg+1}

    // --- init c (registers) and publish h_hist[l][0] ---
    float creg[2][2];
#pragma unroll
    for (int half = 0; half < 2; half++) {
        int u = u0 + 2 * rg + half;
#pragma unroll
        for (int b = 0; b < 2; b++) {
            int bb = b0 + 2 * bg + b;
            creg[half][b] = c0[(l * BATCH + bb) * HID + u];
            g_h[((l * TP1 + 0) * BATCH + bb) * HID + u] =
                h0[(l * BATCH + bb) * HID + u];
        }
    }
    __syncthreads();
    if (tid == 0) red_release_add1(&g_flg[(l * TP1 + 0) * NB + bs]);

    const int kstart = (l == 0) ? HID : 0;
    const int kc = KDIM - kstart;

    for (int t = 0; t < T_STEPS; t++) {
        // ---- tid0 waits for producers (acquire), bar propagates ----
        if (tid == 0) {
            while (ld_acq(&g_flg[(l * TP1 + t) * NB + bs]) < NS) {}
            if (l > 0)
                while (ld_acq(&g_flg[((l - 1) * TP1 + t + 1) * NB + bs]) < NS) {}
        }
        __syncthreads();

        // ---- output head: h3[t] complete => out[t-1] (rotating unit-slice CTA) ----
        if (l == 3 && t > 0 && us == ((t - 1) & 3)) {
            if (tid < 128) {
                int b = tid >> 2, part = tid & 3;     // 32 batches x 4 partials
                const float* hrow =
                    &g_h[((3 * TP1 + t) * BATCH + b0 + b) * HID];
                float s = 0.0f;
#pragma unroll
                for (int j = 0; j < 30; j++) {
                    int u = part + 4 * j;
                    s += hrow[u] * wlin_s[u];
                }
                s += __shfl_down_sync(0xffffffffu, s, 2);
                s += __shfl_down_sync(0xffffffffu, s, 1);
                if (part == 0) out[(t - 1) * BATCH + b0 + b] = s + bl;
            }
        }

        // ---- stage input as duplicated pairs: inp_s[k*IPITCH + 2b] = (v,v) ----
        for (int idx = tid; idx < BS * kc; idx += THREADS) {
            int bb = idx / kc, kr = idx - bb * kc;
            int k = kstart + kr;
            float v;
            if (k < HID)
                v = g_h[(((l - 1) * TP1 + t + 1) * BATCH + b0 + bb) * HID + k];
            else
                v = g_h[((l * TP1 + t) * BATCH + b0 + bb) * HID + (k - HID)];
            *(float2*)&inp_s[k * IPITCH + 2 * bb] = make_float2(v, v);
        }
        __syncthreads();

        // ---- gates GEMM with packed f32x2 FMA; 3 LDS per k ----
        unsigned long long acc2[4][2];
#pragma unroll
        for (int i = 0; i < 4; i++) { acc2[i][0] = 0ULL; acc2[i][1] = 0ULL; }

        for (int k = kstart; k < KDIM; k += 4) {
#pragma unroll
            for (int kk = 0; kk < 4; kk++) {
                const ulonglong2 wA =
                    *(const ulonglong2*)&W_s[(k + kk) * ROWS + rg * 8];
                const ulonglong2 wB =
                    *(const ulonglong2*)&W_s[(k + kk) * ROWS + rg * 8 + 4];
                const ulonglong2 hh =
                    *(const ulonglong2*)&inp_s[(k + kk) * IPITCH + 4 * bg];
                acc2[0][0] = ffma2(wA.x, hh.x, acc2[0][0]);
                acc2[0][1] = ffma2(wA.x, hh.y, acc2[0][1]);
                acc2[1][0] = ffma2(wA.y, hh.x, acc2[1][0]);
                acc2[1][1] = ffma2(wA.y, hh.y, acc2[1][1]);
                acc2[2][0] = ffma2(wB.x, hh.x, acc2[2][0]);
                acc2[2][1] = ffma2(wB.x, hh.y, acc2[2][1]);
                acc2[3][0] = ffma2(wB.y, hh.x, acc2[3][0]);
                acc2[3][1] = ffma2(wB.y, hh.y, acc2[3][1]);
            }
        }

        // ---- elementwise cell update ----
        float xv[2];
        if (l == 0) {
            xv[0] = x[t * BATCH + b0 + 2 * bg];
            xv[1] = x[t * BATCH + b0 + 2 * bg + 1];
        }
#pragma unroll
        for (int half = 0; half < 2; half++) {
            int u = u0 + 2 * rg + half;
#pragma unroll
            for (int b = 0; b < 2; b++) {
                union { unsigned long long u64; float2 f2; } p0, p1;
                p0.u64 = acc2[half * 2 + 0][b];   // (i, f)
                p1.u64 = acc2[half * 2 + 1][b];   // (g, o)
                int r = half * 4;
                float gi = p0.f2.x + bias_s[rg * 8 + r + 0];
                float gf = p0.f2.y + bias_s[rg * 8 + r + 1];
                float gg = p1.f2.x + bias_s[rg * 8 + r + 2];
                float go = p1.f2.y + bias_s[rg * 8 + r + 3];
                if (l == 0) {
                    gi += xv[b] * w0_s[rg * 8 + r + 0];
                    gf += xv[b] * w0_s[rg * 8 + r + 1];
                    gg += xv[b] * w0_s[rg * 8 + r + 2];
                    go += xv[b] * w0_s[rg * 8 + r + 3];
                }
                float cn = sigf(gf) * creg[half][b] + sigf(gi) * tanh_f(gg);
                creg[half][b] = cn;
                float hv = sigf(go) * tanh_f(cn);
                g_h[((l * TP1 + t + 1) * BATCH + b0 + 2 * bg + b) * HID + u] = hv;
            }
        }
        __syncthreads();   // all STG h done; also WAR-protects inp_s
        if (tid == 0) red_release_add1(&g_flg[(l * TP1 + t + 1) * NB + bs]);
    }

    // ---- final output row out[T-1] (us==3 owns it per rotation) ----
    if (l == 3 && us == ((T_STEPS - 1) & 3)) {
        if (tid == 0) {
            while (ld_acq(&g_flg[(3 * TP1 + T_STEPS) * NB + bs]) < NS) {}
        }
        __syncthreads();
        if (tid < 128) {
            int b = tid >> 2, part = tid & 3;
            const float* hrow =
                &g_h[((3 * TP1 + T_STEPS) * BATCH + b0 + b) * HID];
            float s = 0.0f;
#pragma unroll
            for (int j = 0; j < 30; j++) {
                int u = part + 4 * j;
                s += hrow[u] * wlin_s[u];
            }
            s += __shfl_down_sync(0xffffffffu, s, 2);
            s += __shfl_down_sync(0xffffffffu, s, 1);
            if (part == 0) out[(T_STEPS - 1) * BATCH + b0 + b] = s + bl;
        }
    }

    // ---- global done-barrier, then reset flags for the next replay ----
    __syncthreads();
    if (tid == 0) {
        red_release_add1(&g_done[0]);
        while (ld_acq(&g_done[0]) < NCTA) {}
    }
    __syncthreads();
    for (int i = bid * THREADS + tid; i < NFLG; i += NCTA * THREADS)
        g_flg[i] = 0;
    __syncthreads();
    if (tid == 0) {
        red_release_add1(&g_done[1]);
        if (bid == 0) {
            while (ld_acq(&g_done[1]) < NCTA) {}
            g_done[0] = 0;
            g_done[1] = 0;
        }
    }
}

// ---------------- launch (ONE graph node) ----------------
extern "C" void kernel_launch(void* const* d_in, const int* in_sizes, int n_in,
                              void* d_out, int out_size)
{
    const float* x    = (const float*)d_in[0];
    const float* h0   = (const float*)d_in[1];
    const float* c0   = (const float*)d_in[2];
    const float* Wih0 = (const float*)d_in[3];
    const float* Wih  = (const float*)d_in[4];
    const float* Whh  = (const float*)d_in[5];
    const float* bih  = (const float*)d_in[6];
    const float* bhh  = (const float*)d_in[7];
    const float* Wlin = (const float*)d_in[8];
    const float* blin = (const float*)d_in[9];
    float* out = (float*)d_out;

    cudaFuncSetAttribute(lstm_kernel,
                         cudaFuncAttributeMaxDynamicSharedMemorySize,
                         SMEM_BYTES);

    lstm_kernel<<<NCTA, THREADS, SMEM_BYTES>>>(
        x, h0, c0, Wih0, Wih, Whh, bih, bhh, Wlin, blin, out);
}